// round 9
// baseline (speedup 1.0000x reference)
#include <cuda_runtime.h>
#include <math.h>

#define N_NODES 4096
#define C 256
#define NH 4
#define CH 64
#define ALPHA 0.2f
#define NC (N_NODES / 32)

typedef unsigned long long ull;

// ---------------- device scratch (no allocs allowed) ----------------
__device__ float  g_feats[N_NODES * C];     // 4 MB
__device__ float  g_src[N_NODES * NH];
__device__ float4 g_DE[N_NODES * NH];       // (dst, exp(dst), exp(a*dst), -)
__device__ unsigned int g_maxdst_enc[NH];   // monotone-encoded float max

__device__ __forceinline__ unsigned int fenc(float f) {
    unsigned int u = __float_as_uint(f);
    return (u & 0x80000000u) ? ~u : (u | 0x80000000u);
}
__device__ __forceinline__ float fdec(unsigned int u) {
    return (u & 0x80000000u) ? __uint_as_float(u ^ 0x80000000u)
                             : __uint_as_float(~u);
}

__device__ __forceinline__ unsigned int sm32(const void* p) {
    unsigned int a;
    asm("{ .reg .u64 t; cvta.to.shared.u64 t, %1; cvt.u32.u64 %0, t; }"
        : "=r"(a) : "l"(p));
    return a;
}

#define CP_ASYNC16(sa, ga) \
    asm volatile("cp.async.cg.shared.global [%0], [%1], 16;" :: "r"(sa), "l"(ga))
#define CP_COMMIT()  asm volatile("cp.async.commit_group;")
#define CP_WAIT0()   asm volatile("cp.async.wait_group 0;" ::: "memory")

// ---------------- init ----------------
__global__ void init_kernel() {
    if (threadIdx.x < NH) g_maxdst_enc[threadIdx.x] = 0u;
}

// ---------------- phase 1: feats = X @ W + b ----------------
__global__ __launch_bounds__(256) void gemm_feats(
    const float* __restrict__ X, const float* __restrict__ W,
    const float* __restrict__ bias)
{
    __shared__ float As[16][64];
    __shared__ float Bs[16][64];

    const int tid = threadIdx.x;
    const int tx = tid & 15;
    const int ty = tid >> 4;
    const int bm = blockIdx.y * 64;
    const int bn = blockIdx.x * 64;

    float acc[4][4] = {};

    for (int k0 = 0; k0 < C; k0 += 16) {
        {
            int row = tid >> 2;
            int kc  = (tid & 3) * 4;
            float4 v = *(const float4*)&X[(size_t)(bm + row) * C + k0 + kc];
            As[kc + 0][row] = v.x;
            As[kc + 1][row] = v.y;
            As[kc + 2][row] = v.z;
            As[kc + 3][row] = v.w;
        }
        {
            int kr = tid >> 4;
            int cc = (tid & 15) * 4;
            *(float4*)&Bs[kr][cc] =
                *(const float4*)&W[(size_t)(k0 + kr) * C + bn + cc];
        }
        __syncthreads();

#pragma unroll
        for (int kk = 0; kk < 16; kk++) {
            float4 a4 = *(const float4*)&As[kk][ty * 4];
            float4 b4 = *(const float4*)&Bs[kk][tx * 4];
            float av[4] = {a4.x, a4.y, a4.z, a4.w};
            float bv[4] = {b4.x, b4.y, b4.z, b4.w};
#pragma unroll
            for (int i = 0; i < 4; i++)
#pragma unroll
                for (int j = 0; j < 4; j++)
                    acc[i][j] += av[i] * bv[j];
        }
        __syncthreads();
    }

#pragma unroll
    for (int i = 0; i < 4; i++)
#pragma unroll
        for (int j = 0; j < 4; j++) {
            int r = bm + ty * 4 + i;
            int c = bn + tx * 4 + j;
            g_feats[(size_t)r * C + c] = acc[i][j] + bias[c];
        }
}

// ---------------- phase 2: src/dst + exp factors + maxdst ----------------
__global__ __launch_bounds__(256) void srcdst_kernel(const float* __restrict__ a)
{
    const int warp = threadIdx.x >> 5;
    const int lane = threadIdx.x & 31;
    const int n = blockIdx.x * 8 + warp;
    if (n >= N_NODES) return;

    const float* f = g_feats + (size_t)n * C;

#pragma unroll
    for (int h = 0; h < NH; h++) {
        float f0 = f[h * 64 + lane];
        float f1 = f[h * 64 + 32 + lane];
        float as0 = a[h * 128 + lane];
        float as1 = a[h * 128 + 32 + lane];
        float ad0 = a[h * 128 + 64 + lane];
        float ad1 = a[h * 128 + 96 + lane];
        float vs = f0 * as0 + f1 * as1;
        float vd = f0 * ad0 + f1 * ad1;
#pragma unroll
        for (int o = 16; o; o >>= 1) {
            vs += __shfl_xor_sync(0xFFFFFFFFu, vs, o);
            vd += __shfl_xor_sync(0xFFFFFFFFu, vd, o);
        }
        if (lane == 0) {
            g_src[n * NH + h] = vs;
            g_DE[n * NH + h] = make_float4(vd, expf(vd), expf(ALPHA * vd), 0.f);
            atomicMax(&g_maxdst_enc[h], fenc(vd));
        }
    }
}

// ---------------- phase 3: masked-softmax attention + PV (fused) ----------------
// grid (NH, N/128); block 256 threads (8 warps), 1 block/SM, 128 blocks.
// Block tile: 128 i x 64 c (full head); j chunks of 32.
// Warp wq owns a private i-strip [wq*16, wq*16+16). Thread (jj = lane):
//   prob phase : j = j0+jj, its warp's 16 i (adj/DE prefetched in regs)
//   PV phase   : 16 i x 2 c  (16 f32x2 accumulators)
// Probs are warp-private (same warp writes & reads s_probQ) -> __syncwarp only.
// Feats staged global->smem via cp.async (no regs, no STS), double-buffered;
// ONE __syncthreads per chunk. adj/DE LDGs for chunk c+1 issued before PV(c).
__global__ __launch_bounds__(256) void attn_kernel(
    const int* __restrict__ adj, float* __restrict__ out)
{
    __shared__ float  s_feat[2][32][64];    // [buf][j][c]        16 KB
    __shared__ float4 s_probQ[32][32];      // [i-quad][j]        16 KB
    __shared__ float4 s_SPP[128];           // (src, P1, P2, -)    2 KB
    __shared__ float  s_isum[128];

    const int h   = blockIdx.x;
    const int i0  = blockIdx.y * 128;
    const int tid = threadIdx.x;
    const int jj  = tid & 31;
    const int wq  = tid >> 5;
    const int ib  = wq * 16;                // local i base of this warp

    if (tid < 128) {
        float src = g_src[(i0 + tid) * NH + h];
        float md  = fdec(g_maxdst_enc[h]);
        float bb  = src + md;
        bb = (bb >= 0.f) ? bb : ALPHA * bb; // b_i = leaky(src + max_dst) >= all logits
        s_SPP[tid] = make_float4(src, expf(src - bb), expf(ALPHA * src - bb), 0.f);
    }
    __syncthreads();

    ull acc[8][2];
#pragma unroll
    for (int p = 0; p < 8; p++) { acc[p][0] = 0ull; acc[p][1] = 0ull; }
    float psum[16];
#pragma unroll
    for (int k = 0; k < 16; k++) psum[k] = 0.f;

    const float* fbase   = g_feats + h * 64;
    const int*   adjbase = adj + (size_t)(i0 + ib) * N_NODES + jj;

    // feat staging: 2 cp.async.16B per thread cover [32][64]
    const int fr0 = tid >> 4;               // 0..15
    const int fc0 = (tid & 15) * 4;
    const int fr1 = fr0 + 16;               // 16..31
    const unsigned int sA0 = sm32(&s_feat[0][fr0][fc0]);
    const unsigned int sA1 = sm32(&s_feat[0][fr1][fc0]);
    const unsigned int sB0 = sm32(&s_feat[1][fr0][fc0]);
    const unsigned int sB1 = sm32(&s_feat[1][fr1][fc0]);

    // ---- prologue: chunk 0 ----
    CP_ASYNC16(sA0, &fbase[(size_t)fr0 * C + fc0]);
    CP_ASYNC16(sA1, &fbase[(size_t)fr1 * C + fc0]);
    CP_COMMIT();
    int adjreg[16];
#pragma unroll
    for (int k = 0; k < 16; k++) adjreg[k] = adjbase[(size_t)k * N_NODES];
    float4 de = g_DE[jj * NH + h];

    for (int c = 0; c < NC; c++) {
        const int buf = c & 1;

        // ---- probs for chunk c (warp-private region of s_probQ) ----
        __syncwarp();       // prior PV reads of this warp's probQ region done
        {
            float pr[16];
#pragma unroll
            for (int k = 0; k < 16; k++) {
                float4 spp = s_SPP[ib + k];
                float s = spp.x + de.x;
                float p = (adjreg[k] == 1)
                            ? ((s >= 0.f) ? spp.y * de.y : spp.z * de.z)
                            : 0.f;
                pr[k] = p;
                psum[k] += p;
            }
#pragma unroll
            for (int q = 0; q < 4; q++)
                s_probQ[wq * 4 + q][jj] =
                    make_float4(pr[4 * q], pr[4 * q + 1], pr[4 * q + 2], pr[4 * q + 3]);
        }

        CP_WAIT0();          // feat(c) arrived
        __syncthreads();     // feat(c) visible to all; PV(c-1) complete block-wide

        // ---- prefetch chunk c+1 (overlaps PV below) ----
        if (c + 1 < NC) {
            const int j0n = (c + 1) * 32;
            if (buf == 0) {  // next goes to buffer 1
                CP_ASYNC16(sB0, &fbase[(size_t)(j0n + fr0) * C + fc0]);
                CP_ASYNC16(sB1, &fbase[(size_t)(j0n + fr1) * C + fc0]);
            } else {
                CP_ASYNC16(sA0, &fbase[(size_t)(j0n + fr0) * C + fc0]);
                CP_ASYNC16(sA1, &fbase[(size_t)(j0n + fr1) * C + fc0]);
            }
            CP_COMMIT();
#pragma unroll
            for (int k = 0; k < 16; k++)
                adjreg[k] = adjbase[(size_t)k * N_NODES + j0n];
            de = g_DE[(size_t)(j0n + jj) * NH + h];
        }

        // ---- PV chunk c: 16 i x 2 c per thread, packed fp32 FMA ----
#pragma unroll 8
        for (int j = 0; j < 32; j++) {
            float2 fp = *(const float2*)&s_feat[buf][j][jj * 2];
            ull f0, f1;
            asm("mov.b64 %0, {%1, %1};" : "=l"(f0) : "f"(fp.x));
            asm("mov.b64 %0, {%1, %1};" : "=l"(f1) : "f"(fp.y));
            ulonglong2 pa = *(const ulonglong2*)&s_probQ[wq * 4 + 0][j];
            ulonglong2 pb = *(const ulonglong2*)&s_probQ[wq * 4 + 1][j];
            ulonglong2 pc = *(const ulonglong2*)&s_probQ[wq * 4 + 2][j];
            ulonglong2 pd = *(const ulonglong2*)&s_probQ[wq * 4 + 3][j];
            asm("fma.rn.f32x2 %0, %1, %2, %0;" : "+l"(acc[0][0]) : "l"(pa.x), "l"(f0));
            asm("fma.rn.f32x2 %0, %1, %2, %0;" : "+l"(acc[0][1]) : "l"(pa.x), "l"(f1));
            asm("fma.rn.f32x2 %0, %1, %2, %0;" : "+l"(acc[1][0]) : "l"(pa.y), "l"(f0));
            asm("fma.rn.f32x2 %0, %1, %2, %0;" : "+l"(acc[1][1]) : "l"(pa.y), "l"(f1));
            asm("fma.rn.f32x2 %0, %1, %2, %0;" : "+l"(acc[2][0]) : "l"(pb.x), "l"(f0));
            asm("fma.rn.f32x2 %0, %1, %2, %0;" : "+l"(acc[2][1]) : "l"(pb.x), "l"(f1));
            asm("fma.rn.f32x2 %0, %1, %2, %0;" : "+l"(acc[3][0]) : "l"(pb.y), "l"(f0));
            asm("fma.rn.f32x2 %0, %1, %2, %0;" : "+l"(acc[3][1]) : "l"(pb.y), "l"(f1));
            asm("fma.rn.f32x2 %0, %1, %2, %0;" : "+l"(acc[4][0]) : "l"(pc.x), "l"(f0));
            asm("fma.rn.f32x2 %0, %1, %2, %0;" : "+l"(acc[4][1]) : "l"(pc.x), "l"(f1));
            asm("fma.rn.f32x2 %0, %1, %2, %0;" : "+l"(acc[5][0]) : "l"(pc.y), "l"(f0));
            asm("fma.rn.f32x2 %0, %1, %2, %0;" : "+l"(acc[5][1]) : "l"(pc.y), "l"(f1));
            asm("fma.rn.f32x2 %0, %1, %2, %0;" : "+l"(acc[6][0]) : "l"(pd.x), "l"(f0));
            asm("fma.rn.f32x2 %0, %1, %2, %0;" : "+l"(acc[6][1]) : "l"(pd.x), "l"(f1));
            asm("fma.rn.f32x2 %0, %1, %2, %0;" : "+l"(acc[7][0]) : "l"(pd.y), "l"(f0));
            asm("fma.rn.f32x2 %0, %1, %2, %0;" : "+l"(acc[7][1]) : "l"(pd.y), "l"(f1));
        }
    }

    // ---- denominators: reduce psum over the 32 lanes ----
#pragma unroll
    for (int k = 0; k < 16; k++) {
        float v = psum[k];
#pragma unroll
        for (int o = 16; o; o >>= 1) v += __shfl_xor_sync(0xFFFFFFFFu, v, o);
        if (jj == 0) s_isum[ib + k] = 1.f / v;
    }
    __syncthreads();

    // ---- write normalized output (float2 stores, coalesced per warp) ----
#pragma unroll
    for (int p = 0; p < 8; p++) {
        int iloc = ib + 2 * p;
        float r0 = s_isum[iloc];
        float r1 = s_isum[iloc + 1];
        float a0lo, a0hi, a1lo, a1hi;
        asm("mov.b64 {%0, %1}, %2;" : "=f"(a0lo), "=f"(a0hi) : "l"(acc[p][0]));
        asm("mov.b64 {%0, %1}, %2;" : "=f"(a1lo), "=f"(a1hi) : "l"(acc[p][1]));
        float2 v0 = make_float2(a0lo * r0, a1lo * r0);
        float2 v1 = make_float2(a0hi * r1, a1hi * r1);
        *(float2*)&out[(size_t)(i0 + iloc) * C + h * 64 + jj * 2]     = v0;
        *(float2*)&out[(size_t)(i0 + iloc + 1) * C + h * 64 + jj * 2] = v1;
    }
}

// ---------------- launch ----------------
extern "C" void kernel_launch(void* const* d_in, const int* in_sizes, int n_in,
                              void* d_out, int out_size)
{
    const float* node_feats = (const float*)d_in[0];
    const int*   adj        = (const int*)d_in[1];
    const float* W          = (const float*)d_in[2];
    const float* b          = (const float*)d_in[3];
    const float* a          = (const float*)d_in[4];
    float* out = (float*)d_out;

    init_kernel<<<1, 32>>>();
    gemm_feats<<<dim3(C / 64, N_NODES / 64), 256>>>(node_feats, W, b);
    srcdst_kernel<<<N_NODES / 8, 256>>>(a);
    attn_kernel<<<dim3(NH, N_NODES / 128), 256>>>(adj, out);
}

// round 10
// speedup vs baseline: 1.2468x; 1.2468x over previous
#include <cuda_runtime.h>
#include <math.h>

#define N_NODES 4096
#define C 256
#define NH 4
#define CH 64
#define ALPHA 0.2f
#define NSPLIT 2
#define NCPART (N_NODES / 32 / NSPLIT)   // 64 chunks of 32 j per split

typedef unsigned long long ull;

// ---------------- device scratch (no allocs allowed) ----------------
__device__ float  g_feats[N_NODES * C];             // 4 MB
__device__ float  g_src[N_NODES * NH];
__device__ float4 g_DE[N_NODES * NH];               // (dst, e^dst, e^(a*dst), -)
__device__ unsigned int g_maxdst_enc[NH];
__device__ float  g_pacc[NSPLIT][N_NODES * C];      // 8 MB unnormalized partials
__device__ float  g_pden[NSPLIT][N_NODES * NH];     // partial denominators

__device__ __forceinline__ unsigned int fenc(float f) {
    unsigned int u = __float_as_uint(f);
    return (u & 0x80000000u) ? ~u : (u | 0x80000000u);
}
__device__ __forceinline__ float fdec(unsigned int u) {
    return (u & 0x80000000u) ? __uint_as_float(u ^ 0x80000000u)
                             : __uint_as_float(~u);
}

__device__ __forceinline__ unsigned int sm32(const void* p) {
    unsigned int a;
    asm("{ .reg .u64 t; cvta.to.shared.u64 t, %1; cvt.u32.u64 %0, t; }"
        : "=r"(a) : "l"(p));
    return a;
}

#define CP_ASYNC16(sa, ga) \
    asm volatile("cp.async.cg.shared.global [%0], [%1], 16;" :: "r"(sa), "l"(ga))
#define CP_COMMIT()  asm volatile("cp.async.commit_group;")
#define CP_WAIT0()   asm volatile("cp.async.wait_group 0;" ::: "memory")

// ---------------- init ----------------
__global__ void init_kernel() {
    if (threadIdx.x < NH) g_maxdst_enc[threadIdx.x] = 0u;
}

// ---------------- phase 1: feats = X @ W + b ----------------
__global__ __launch_bounds__(256) void gemm_feats(
    const float* __restrict__ X, const float* __restrict__ W,
    const float* __restrict__ bias)
{
    __shared__ float As[16][64];
    __shared__ float Bs[16][64];

    const int tid = threadIdx.x;
    const int tx = tid & 15;
    const int ty = tid >> 4;
    const int bm = blockIdx.y * 64;
    const int bn = blockIdx.x * 64;

    float acc[4][4] = {};

    for (int k0 = 0; k0 < C; k0 += 16) {
        {
            int row = tid >> 2;
            int kc  = (tid & 3) * 4;
            float4 v = *(const float4*)&X[(size_t)(bm + row) * C + k0 + kc];
            As[kc + 0][row] = v.x;
            As[kc + 1][row] = v.y;
            As[kc + 2][row] = v.z;
            As[kc + 3][row] = v.w;
        }
        {
            int kr = tid >> 4;
            int cc = (tid & 15) * 4;
            *(float4*)&Bs[kr][cc] =
                *(const float4*)&W[(size_t)(k0 + kr) * C + bn + cc];
        }
        __syncthreads();

#pragma unroll
        for (int kk = 0; kk < 16; kk++) {
            float4 a4 = *(const float4*)&As[kk][ty * 4];
            float4 b4 = *(const float4*)&Bs[kk][tx * 4];
            float av[4] = {a4.x, a4.y, a4.z, a4.w};
            float bv[4] = {b4.x, b4.y, b4.z, b4.w};
#pragma unroll
            for (int i = 0; i < 4; i++)
#pragma unroll
                for (int j = 0; j < 4; j++)
                    acc[i][j] += av[i] * bv[j];
        }
        __syncthreads();
    }

#pragma unroll
    for (int i = 0; i < 4; i++)
#pragma unroll
        for (int j = 0; j < 4; j++) {
            int r = bm + ty * 4 + i;
            int c = bn + tx * 4 + j;
            g_feats[(size_t)r * C + c] = acc[i][j] + bias[c];
        }
}

// ---------------- phase 2: src/dst + exp factors + maxdst ----------------
__global__ __launch_bounds__(256) void srcdst_kernel(const float* __restrict__ a)
{
    const int warp = threadIdx.x >> 5;
    const int lane = threadIdx.x & 31;
    const int n = blockIdx.x * 8 + warp;
    if (n >= N_NODES) return;

    const float* f = g_feats + (size_t)n * C;

#pragma unroll
    for (int h = 0; h < NH; h++) {
        float f0 = f[h * 64 + lane];
        float f1 = f[h * 64 + 32 + lane];
        float as0 = a[h * 128 + lane];
        float as1 = a[h * 128 + 32 + lane];
        float ad0 = a[h * 128 + 64 + lane];
        float ad1 = a[h * 128 + 96 + lane];
        float vs = f0 * as0 + f1 * as1;
        float vd = f0 * ad0 + f1 * ad1;
#pragma unroll
        for (int o = 16; o; o >>= 1) {
            vs += __shfl_xor_sync(0xFFFFFFFFu, vs, o);
            vd += __shfl_xor_sync(0xFFFFFFFFu, vd, o);
        }
        if (lane == 0) {
            g_src[n * NH + h] = vs;
            g_DE[n * NH + h] = make_float4(vd, expf(vd), expf(ALPHA * vd), 0.f);
            atomicMax(&g_maxdst_enc[h], fenc(vd));
        }
    }
}

// ---------------- phase 3: masked-softmax attention + PV (split-j) ----------------
// grid (NH, N/128, NSPLIT); block 256 threads (8 warps), 2 blocks/SM.
// Block tile: 128 i x 64 c (full head); j range [z*2048, z*2048+2048) in 32-chunks.
// Warp wq owns i-strip [wq*16, +16). Thread (jj = lane):
//   prob phase : j = j0+jj, its warp's 16 i (adj/DE prefetched in regs)
//   PV phase   : 16 i x 2 c  (16 f32x2 accumulators)
// Probs are warp-private -> __syncwarp only. Feats via cp.async double-buffer;
// one __syncthreads per chunk. Writes UNNORMALIZED partials + denominators.
__global__ __launch_bounds__(256) void attn_kernel(const int* __restrict__ adj)
{
    __shared__ float  s_feat[2][32][64];    // 16 KB
    __shared__ float4 s_probQ[32][32];      // 16 KB
    __shared__ float4 s_SPP[128];           //  2 KB
    __shared__ float  s_den[128];

    const int h   = blockIdx.x;
    const int i0  = blockIdx.y * 128;
    const int sp  = blockIdx.z;
    const int jb  = sp * (N_NODES / NSPLIT);   // j base of this split
    const int tid = threadIdx.x;
    const int jj  = tid & 31;
    const int wq  = tid >> 5;
    const int ib  = wq * 16;

    if (tid < 128) {
        float src = g_src[(i0 + tid) * NH + h];
        float md  = fdec(g_maxdst_enc[h]);
        float bb  = src + md;
        bb = (bb >= 0.f) ? bb : ALPHA * bb;   // b_i >= all logits (both splits!)
        s_SPP[tid] = make_float4(src, expf(src - bb), expf(ALPHA * src - bb), 0.f);
    }
    __syncthreads();

    ull acc[8][2];
#pragma unroll
    for (int p = 0; p < 8; p++) { acc[p][0] = 0ull; acc[p][1] = 0ull; }
    float psum[16];
#pragma unroll
    for (int k = 0; k < 16; k++) psum[k] = 0.f;

    const float* fbase   = g_feats + (size_t)jb * C + h * 64;
    const int*   adjbase = adj + (size_t)(i0 + ib) * N_NODES + jb + jj;

    // feat staging: 2 cp.async.16B per thread cover [32][64]
    const int fr0 = tid >> 4;               // 0..15
    const int fc0 = (tid & 15) * 4;
    const int fr1 = fr0 + 16;               // 16..31
    const unsigned int sA0 = sm32(&s_feat[0][fr0][fc0]);
    const unsigned int sA1 = sm32(&s_feat[0][fr1][fc0]);
    const unsigned int sB0 = sm32(&s_feat[1][fr0][fc0]);
    const unsigned int sB1 = sm32(&s_feat[1][fr1][fc0]);

    // ---- prologue: chunk 0 of this split ----
    CP_ASYNC16(sA0, &fbase[(size_t)fr0 * C + fc0]);
    CP_ASYNC16(sA1, &fbase[(size_t)fr1 * C + fc0]);
    CP_COMMIT();
    int adjreg[16];
#pragma unroll
    for (int k = 0; k < 16; k++) adjreg[k] = adjbase[(size_t)k * N_NODES];
    float4 de = g_DE[(jb + jj) * NH + h];

    for (int c = 0; c < NCPART; c++) {
        const int buf = c & 1;

        // ---- probs for chunk c (warp-private region of s_probQ) ----
        __syncwarp();
        {
            float pr[16];
#pragma unroll
            for (int k = 0; k < 16; k++) {
                float4 spp = s_SPP[ib + k];
                float s = spp.x + de.x;
                float p = (adjreg[k] == 1)
                            ? ((s >= 0.f) ? spp.y * de.y : spp.z * de.z)
                            : 0.f;
                pr[k] = p;
                psum[k] += p;
            }
#pragma unroll
            for (int q = 0; q < 4; q++)
                s_probQ[wq * 4 + q][jj] =
                    make_float4(pr[4 * q], pr[4 * q + 1], pr[4 * q + 2], pr[4 * q + 3]);
        }

        CP_WAIT0();
        __syncthreads();

        // ---- prefetch chunk c+1 (overlaps PV below) ----
        if (c + 1 < NCPART) {
            const int j0n = (c + 1) * 32;
            if (buf == 0) {
                CP_ASYNC16(sB0, &fbase[(size_t)(j0n + fr0) * C + fc0]);
                CP_ASYNC16(sB1, &fbase[(size_t)(j0n + fr1) * C + fc0]);
            } else {
                CP_ASYNC16(sA0, &fbase[(size_t)(j0n + fr0) * C + fc0]);
                CP_ASYNC16(sA1, &fbase[(size_t)(j0n + fr1) * C + fc0]);
            }
            CP_COMMIT();
#pragma unroll
            for (int k = 0; k < 16; k++)
                adjreg[k] = adjbase[(size_t)k * N_NODES + j0n];
            de = g_DE[(size_t)(jb + j0n + jj) * NH + h];
        }

        // ---- PV chunk c: 16 i x 2 c per thread, packed fp32 FMA ----
#pragma unroll 8
        for (int j = 0; j < 32; j++) {
            float2 fp = *(const float2*)&s_feat[buf][j][jj * 2];
            ull f0, f1;
            asm("mov.b64 %0, {%1, %1};" : "=l"(f0) : "f"(fp.x));
            asm("mov.b64 %0, {%1, %1};" : "=l"(f1) : "f"(fp.y));
            ulonglong2 pa = *(const ulonglong2*)&s_probQ[wq * 4 + 0][j];
            ulonglong2 pb = *(const ulonglong2*)&s_probQ[wq * 4 + 1][j];
            ulonglong2 pc = *(const ulonglong2*)&s_probQ[wq * 4 + 2][j];
            ulonglong2 pd = *(const ulonglong2*)&s_probQ[wq * 4 + 3][j];
            asm("fma.rn.f32x2 %0, %1, %2, %0;" : "+l"(acc[0][0]) : "l"(pa.x), "l"(f0));
            asm("fma.rn.f32x2 %0, %1, %2, %0;" : "+l"(acc[0][1]) : "l"(pa.x), "l"(f1));
            asm("fma.rn.f32x2 %0, %1, %2, %0;" : "+l"(acc[1][0]) : "l"(pa.y), "l"(f0));
            asm("fma.rn.f32x2 %0, %1, %2, %0;" : "+l"(acc[1][1]) : "l"(pa.y), "l"(f1));
            asm("fma.rn.f32x2 %0, %1, %2, %0;" : "+l"(acc[2][0]) : "l"(pb.x), "l"(f0));
            asm("fma.rn.f32x2 %0, %1, %2, %0;" : "+l"(acc[2][1]) : "l"(pb.x), "l"(f1));
            asm("fma.rn.f32x2 %0, %1, %2, %0;" : "+l"(acc[3][0]) : "l"(pb.y), "l"(f0));
            asm("fma.rn.f32x2 %0, %1, %2, %0;" : "+l"(acc[3][1]) : "l"(pb.y), "l"(f1));
            asm("fma.rn.f32x2 %0, %1, %2, %0;" : "+l"(acc[4][0]) : "l"(pc.x), "l"(f0));
            asm("fma.rn.f32x2 %0, %1, %2, %0;" : "+l"(acc[4][1]) : "l"(pc.x), "l"(f1));
            asm("fma.rn.f32x2 %0, %1, %2, %0;" : "+l"(acc[5][0]) : "l"(pc.y), "l"(f0));
            asm("fma.rn.f32x2 %0, %1, %2, %0;" : "+l"(acc[5][1]) : "l"(pc.y), "l"(f1));
            asm("fma.rn.f32x2 %0, %1, %2, %0;" : "+l"(acc[6][0]) : "l"(pd.x), "l"(f0));
            asm("fma.rn.f32x2 %0, %1, %2, %0;" : "+l"(acc[6][1]) : "l"(pd.x), "l"(f1));
            asm("fma.rn.f32x2 %0, %1, %2, %0;" : "+l"(acc[7][0]) : "l"(pd.y), "l"(f0));
            asm("fma.rn.f32x2 %0, %1, %2, %0;" : "+l"(acc[7][1]) : "l"(pd.y), "l"(f1));
        }
    }

    // ---- partial denominators ----
#pragma unroll
    for (int k = 0; k < 16; k++) {
        float v = psum[k];
#pragma unroll
        for (int o = 16; o; o >>= 1) v += __shfl_xor_sync(0xFFFFFFFFu, v, o);
        if (jj == 0) {
            s_den[ib + k] = v;   // unused, keeps symmetry
            g_pden[sp][(i0 + ib + k) * NH + h] = v;
        }
    }

    // ---- write unnormalized partial accumulators (float2, coalesced) ----
    float* pacc = g_pacc[sp];
#pragma unroll
    for (int p = 0; p < 8; p++) {
        int iloc = ib + 2 * p;
        float a0lo, a0hi, a1lo, a1hi;
        asm("mov.b64 {%0, %1}, %2;" : "=f"(a0lo), "=f"(a0hi) : "l"(acc[p][0]));
        asm("mov.b64 {%0, %1}, %2;" : "=f"(a1lo), "=f"(a1hi) : "l"(acc[p][1]));
        *(float2*)&pacc[(size_t)(i0 + iloc) * C + h * 64 + jj * 2] =
            make_float2(a0lo, a1lo);
        *(float2*)&pacc[(size_t)(i0 + iloc + 1) * C + h * 64 + jj * 2] =
            make_float2(a0hi, a1hi);
    }
}

// ---------------- phase 4: combine splits + normalize ----------------
// out[i, h*64+c] = (p0 + p1) / (d0 + d1); one float4 per thread.
__global__ __launch_bounds__(256) void combine_kernel(float* __restrict__ out)
{
    int idx = blockIdx.x * 256 + threadIdx.x;       // over N*C/4 float4 groups
    int i = idx >> 6;
    int h = (idx >> 4) & 3;
    float4 a = *(const float4*)&g_pacc[0][(size_t)idx * 4];
    float4 b = *(const float4*)&g_pacc[1][(size_t)idx * 4];
    float r = 1.f / (g_pden[0][i * NH + h] + g_pden[1][i * NH + h]);
    float4 v = make_float4((a.x + b.x) * r, (a.y + b.y) * r,
                           (a.z + b.z) * r, (a.w + b.w) * r);
    *(float4*)&out[(size_t)idx * 4] = v;
}

// ---------------- launch ----------------
extern "C" void kernel_launch(void* const* d_in, const int* in_sizes, int n_in,
                              void* d_out, int out_size)
{
    const float* node_feats = (const float*)d_in[0];
    const int*   adj        = (const int*)d_in[1];
    const float* W          = (const float*)d_in[2];
    const float* b          = (const float*)d_in[3];
    const float* a          = (const float*)d_in[4];
    float* out = (float*)d_out;

    init_kernel<<<1, 32>>>();
    gemm_feats<<<dim3(C / 64, N_NODES / 64), 256>>>(node_feats, W, b);
    srcdst_kernel<<<N_NODES / 8, 256>>>(a);
    attn_kernel<<<dim3(NH, N_NODES / 128, NSPLIT), 256>>>(adj);
    combine_kernel<<<(N_NODES * C / 4) / 256, 256>>>(out);
}

// round 11
// speedup vs baseline: 1.2880x; 1.0331x over previous
#include <cuda_runtime.h>
#include <math.h>

#define N_NODES 4096
#define C 256
#define NH 4
#define CH 64
#define ALPHA 0.2f
#define NSPLIT 2
#define NCPART (N_NODES / 32 / NSPLIT)   // 64 chunks of 32 j per split

typedef unsigned long long ull;

// ---------------- device scratch (no allocs allowed) ----------------
__device__ float  g_feats[N_NODES * C];             // 4 MB
__device__ float  g_src[N_NODES * NH];
__device__ float4 g_DE[N_NODES * NH];               // (dst, e^dst, e^(a*dst), -)
__device__ unsigned int g_maxdst_enc[NH];
__device__ float  g_pacc[NSPLIT][N_NODES * C];      // 8 MB unnormalized partials
__device__ float  g_pden[NSPLIT][N_NODES * NH];     // partial denominators

__device__ __forceinline__ unsigned int fenc(float f) {
    unsigned int u = __float_as_uint(f);
    return (u & 0x80000000u) ? ~u : (u | 0x80000000u);
}
__device__ __forceinline__ float fdec(unsigned int u) {
    return (u & 0x80000000u) ? __uint_as_float(u ^ 0x80000000u)
                             : __uint_as_float(~u);
}

__device__ __forceinline__ unsigned int sm32(const void* p) {
    unsigned int a;
    asm("{ .reg .u64 t; cvta.to.shared.u64 t, %1; cvt.u32.u64 %0, t; }"
        : "=r"(a) : "l"(p));
    return a;
}

#define CP_ASYNC16(sa, ga) \
    asm volatile("cp.async.cg.shared.global [%0], [%1], 16;" :: "r"(sa), "l"(ga))
#define CP_COMMIT()  asm volatile("cp.async.commit_group;")
#define CP_WAIT0()   asm volatile("cp.async.wait_group 0;" ::: "memory")

// ---------------- init ----------------
__global__ void init_kernel() {
    if (threadIdx.x < NH) g_maxdst_enc[threadIdx.x] = 0u;
}

// ---------------- phase 1: feats = X @ W + b ----------------
__global__ __launch_bounds__(256) void gemm_feats(
    const float* __restrict__ X, const float* __restrict__ W,
    const float* __restrict__ bias)
{
    __shared__ float As[16][64];
    __shared__ float Bs[16][64];

    const int tid = threadIdx.x;
    const int tx = tid & 15;
    const int ty = tid >> 4;
    const int bm = blockIdx.y * 64;
    const int bn = blockIdx.x * 64;

    float acc[4][4] = {};

    for (int k0 = 0; k0 < C; k0 += 16) {
        {
            int row = tid >> 2;
            int kc  = (tid & 3) * 4;
            float4 v = *(const float4*)&X[(size_t)(bm + row) * C + k0 + kc];
            As[kc + 0][row] = v.x;
            As[kc + 1][row] = v.y;
            As[kc + 2][row] = v.z;
            As[kc + 3][row] = v.w;
        }
        {
            int kr = tid >> 4;
            int cc = (tid & 15) * 4;
            *(float4*)&Bs[kr][cc] =
                *(const float4*)&W[(size_t)(k0 + kr) * C + bn + cc];
        }
        __syncthreads();

#pragma unroll
        for (int kk = 0; kk < 16; kk++) {
            float4 a4 = *(const float4*)&As[kk][ty * 4];
            float4 b4 = *(const float4*)&Bs[kk][tx * 4];
            float av[4] = {a4.x, a4.y, a4.z, a4.w};
            float bv[4] = {b4.x, b4.y, b4.z, b4.w};
#pragma unroll
            for (int i = 0; i < 4; i++)
#pragma unroll
                for (int j = 0; j < 4; j++)
                    acc[i][j] += av[i] * bv[j];
        }
        __syncthreads();
    }

#pragma unroll
    for (int i = 0; i < 4; i++)
#pragma unroll
        for (int j = 0; j < 4; j++) {
            int r = bm + ty * 4 + i;
            int c = bn + tx * 4 + j;
            g_feats[(size_t)r * C + c] = acc[i][j] + bias[c];
        }
}

// ---------------- phase 2: src/dst + exp factors + maxdst ----------------
__global__ __launch_bounds__(256) void srcdst_kernel(const float* __restrict__ a)
{
    const int warp = threadIdx.x >> 5;
    const int lane = threadIdx.x & 31;
    const int n = blockIdx.x * 8 + warp;
    if (n >= N_NODES) return;

    const float* f = g_feats + (size_t)n * C;

#pragma unroll
    for (int h = 0; h < NH; h++) {
        float f0 = f[h * 64 + lane];
        float f1 = f[h * 64 + 32 + lane];
        float as0 = a[h * 128 + lane];
        float as1 = a[h * 128 + 32 + lane];
        float ad0 = a[h * 128 + 64 + lane];
        float ad1 = a[h * 128 + 96 + lane];
        float vs = f0 * as0 + f1 * as1;
        float vd = f0 * ad0 + f1 * ad1;
#pragma unroll
        for (int o = 16; o; o >>= 1) {
            vs += __shfl_xor_sync(0xFFFFFFFFu, vs, o);
            vd += __shfl_xor_sync(0xFFFFFFFFu, vd, o);
        }
        if (lane == 0) {
            g_src[n * NH + h] = vs;
            g_DE[n * NH + h] = make_float4(vd, expf(vd), expf(ALPHA * vd), 0.f);
            atomicMax(&g_maxdst_enc[h], fenc(vd));
        }
    }
}

// ---------------- phase 3: masked-softmax attention + PV (split-j) ----------------
// grid (NH, N/128, NSPLIT); block 256 threads (8 warps), 2 blocks/SM.
// Block tile: 128 i x 64 c; j range per split in 32-chunks.
// Warp wq owns i-strip [wq*16, +16). PV lane map: cg = lane&15 (4 c each),
// ig = lane>>4 (8 i each) -> per-j smem traffic: feat 2 wf + probs 2 wf
// (half-broadcast LDS.128; row pad 33*float4 avoids the 2-row bank collision).
// Prob phase: lane jj computes its warp's 16 i for j=j0+jj (adj/DE in regs).
// Probs warp-private -> __syncwarp only. Feats via cp.async double-buffer;
// one __syncthreads per chunk. Writes UNNORMALIZED partials + denominators.
__global__ __launch_bounds__(256) void attn_kernel(const int* __restrict__ adj)
{
    __shared__ float  s_feat[2][32][64];    // 16 KB
    __shared__ float4 s_probQ[32][33];      // 16.5 KB  [i-quad][j], padded row
    __shared__ float4 s_SPP[128];           //  2 KB (src, P1, P2, -)

    const int h   = blockIdx.x;
    const int i0  = blockIdx.y * 128;
    const int sp  = blockIdx.z;
    const int jb  = sp * (N_NODES / NSPLIT);   // j base of this split
    const int tid = threadIdx.x;
    const int jj  = tid & 31;
    const int wq  = tid >> 5;
    const int ib  = wq * 16;                   // warp i-strip base
    const int cg  = jj & 15;                   // c-quad (4 c)
    const int ig  = jj >> 4;                   // i-group (8 i)

    if (tid < 128) {
        float src = g_src[(i0 + tid) * NH + h];
        float md  = fdec(g_maxdst_enc[h]);
        float bb  = src + md;
        bb = (bb >= 0.f) ? bb : ALPHA * bb;   // b_i >= all logits (both splits!)
        s_SPP[tid] = make_float4(src, expf(src - bb), expf(ALPHA * src - bb), 0.f);
    }
    __syncthreads();

    ull acc[4][4];                            // [i-pair][c] : 8 i x 4 c
#pragma unroll
    for (int p = 0; p < 4; p++)
#pragma unroll
        for (int q = 0; q < 4; q++) acc[p][q] = 0ull;
    float psum[16];
#pragma unroll
    for (int k = 0; k < 16; k++) psum[k] = 0.f;

    const float* fbase   = g_feats + (size_t)jb * C + h * 64;
    const int*   adjbase = adj + (size_t)(i0 + ib) * N_NODES + jb + jj;

    // feat staging: 2 cp.async.16B per thread cover [32][64]
    const int fr0 = tid >> 4;               // 0..15
    const int fc0 = (tid & 15) * 4;
    const int fr1 = fr0 + 16;               // 16..31
    const unsigned int sA0 = sm32(&s_feat[0][fr0][fc0]);
    const unsigned int sA1 = sm32(&s_feat[0][fr1][fc0]);
    const unsigned int sB0 = sm32(&s_feat[1][fr0][fc0]);
    const unsigned int sB1 = sm32(&s_feat[1][fr1][fc0]);

    // ---- prologue: chunk 0 of this split ----
    CP_ASYNC16(sA0, &fbase[(size_t)fr0 * C + fc0]);
    CP_ASYNC16(sA1, &fbase[(size_t)fr1 * C + fc0]);
    CP_COMMIT();
    int adjreg[16];
#pragma unroll
    for (int k = 0; k < 16; k++) adjreg[k] = adjbase[(size_t)k * N_NODES];
    float4 de = g_DE[(jb + jj) * NH + h];

    const int rowA = wq * 4 + 2 * ig;        // this thread's 2 prob rows
    const int rowB = rowA + 1;

    for (int c = 0; c < NCPART; c++) {
        const int buf = c & 1;

        // ---- probs for chunk c (warp-private region of s_probQ) ----
        __syncwarp();
        {
            float pr[16];
#pragma unroll
            for (int k = 0; k < 16; k++) {
                float4 spp = s_SPP[ib + k];
                float s = spp.x + de.x;
                float p = (adjreg[k] == 1)
                            ? ((s >= 0.f) ? spp.y * de.y : spp.z * de.z)
                            : 0.f;
                pr[k] = p;
                psum[k] += p;
            }
#pragma unroll
            for (int q = 0; q < 4; q++)
                s_probQ[wq * 4 + q][jj] =
                    make_float4(pr[4 * q], pr[4 * q + 1], pr[4 * q + 2], pr[4 * q + 3]);
        }

        CP_WAIT0();
        __syncthreads();

        // ---- prefetch chunk c+1 (overlaps PV below) ----
        if (c + 1 < NCPART) {
            const int j0n = (c + 1) * 32;
            if (buf == 0) {
                CP_ASYNC16(sB0, &fbase[(size_t)(j0n + fr0) * C + fc0]);
                CP_ASYNC16(sB1, &fbase[(size_t)(j0n + fr1) * C + fc0]);
            } else {
                CP_ASYNC16(sA0, &fbase[(size_t)(j0n + fr0) * C + fc0]);
                CP_ASYNC16(sA1, &fbase[(size_t)(j0n + fr1) * C + fc0]);
            }
            CP_COMMIT();
#pragma unroll
            for (int k = 0; k < 16; k++)
                adjreg[k] = adjbase[(size_t)k * N_NODES + j0n];
            de = g_DE[(size_t)(jb + j0n + jj) * NH + h];
        }

        // ---- PV chunk c: 8 i x 4 c per thread, packed fp32 FMA ----
#pragma unroll 8
        for (int j = 0; j < 32; j++) {
            float4 fq = *(const float4*)&s_feat[buf][j][cg * 4];
            ull f0, f1, f2, f3;
            asm("mov.b64 %0, {%1, %1};" : "=l"(f0) : "f"(fq.x));
            asm("mov.b64 %0, {%1, %1};" : "=l"(f1) : "f"(fq.y));
            asm("mov.b64 %0, {%1, %1};" : "=l"(f2) : "f"(fq.z));
            asm("mov.b64 %0, {%1, %1};" : "=l"(f3) : "f"(fq.w));
            ulonglong2 pA = *(const ulonglong2*)&s_probQ[rowA][j];  // i-pairs 0,1
            ulonglong2 pB = *(const ulonglong2*)&s_probQ[rowB][j];  // i-pairs 2,3
            asm("fma.rn.f32x2 %0, %1, %2, %0;" : "+l"(acc[0][0]) : "l"(pA.x), "l"(f0));
            asm("fma.rn.f32x2 %0, %1, %2, %0;" : "+l"(acc[0][1]) : "l"(pA.x), "l"(f1));
            asm("fma.rn.f32x2 %0, %1, %2, %0;" : "+l"(acc[0][2]) : "l"(pA.x), "l"(f2));
            asm("fma.rn.f32x2 %0, %1, %2, %0;" : "+l"(acc[0][3]) : "l"(pA.x), "l"(f3));
            asm("fma.rn.f32x2 %0, %1, %2, %0;" : "+l"(acc[1][0]) : "l"(pA.y), "l"(f0));
            asm("fma.rn.f32x2 %0, %1, %2, %0;" : "+l"(acc[1][1]) : "l"(pA.y), "l"(f1));
            asm("fma.rn.f32x2 %0, %1, %2, %0;" : "+l"(acc[1][2]) : "l"(pA.y), "l"(f2));
            asm("fma.rn.f32x2 %0, %1, %2, %0;" : "+l"(acc[1][3]) : "l"(pA.y), "l"(f3));
            asm("fma.rn.f32x2 %0, %1, %2, %0;" : "+l"(acc[2][0]) : "l"(pB.x), "l"(f0));
            asm("fma.rn.f32x2 %0, %1, %2, %0;" : "+l"(acc[2][1]) : "l"(pB.x), "l"(f1));
            asm("fma.rn.f32x2 %0, %1, %2, %0;" : "+l"(acc[2][2]) : "l"(pB.x), "l"(f2));
            asm("fma.rn.f32x2 %0, %1, %2, %0;" : "+l"(acc[2][3]) : "l"(pB.x), "l"(f3));
            asm("fma.rn.f32x2 %0, %1, %2, %0;" : "+l"(acc[3][0]) : "l"(pB.y), "l"(f0));
            asm("fma.rn.f32x2 %0, %1, %2, %0;" : "+l"(acc[3][1]) : "l"(pB.y), "l"(f1));
            asm("fma.rn.f32x2 %0, %1, %2, %0;" : "+l"(acc[3][2]) : "l"(pB.y), "l"(f2));
            asm("fma.rn.f32x2 %0, %1, %2, %0;" : "+l"(acc[3][3]) : "l"(pB.y), "l"(f3));
        }
    }

    // ---- partial denominators ----
#pragma unroll
    for (int k = 0; k < 16; k++) {
        float v = psum[k];
#pragma unroll
        for (int o = 16; o; o >>= 1) v += __shfl_xor_sync(0xFFFFFFFFu, v, o);
        if (jj == 0) g_pden[sp][(i0 + ib + k) * NH + h] = v;
    }

    // ---- write unnormalized partial accumulators (float4, coalesced) ----
    float* pacc = g_pacc[sp];
#pragma unroll
    for (int p = 0; p < 4; p++) {
        int iloc = ib + ig * 8 + 2 * p;
        float lo[4], hi[4];
#pragma unroll
        for (int q = 0; q < 4; q++)
            asm("mov.b64 {%0, %1}, %2;" : "=f"(lo[q]), "=f"(hi[q]) : "l"(acc[p][q]));
        *(float4*)&pacc[(size_t)(i0 + iloc) * C + h * 64 + cg * 4] =
            make_float4(lo[0], lo[1], lo[2], lo[3]);
        *(float4*)&pacc[(size_t)(i0 + iloc + 1) * C + h * 64 + cg * 4] =
            make_float4(hi[0], hi[1], hi[2], hi[3]);
    }
}

// ---------------- phase 4: combine splits + normalize ----------------
__global__ __launch_bounds__(256) void combine_kernel(float* __restrict__ out)
{
    int idx = blockIdx.x * 256 + threadIdx.x;       // over N*C/4 float4 groups
    int i = idx >> 6;
    int h = (idx >> 4) & 3;
    float4 a = *(const float4*)&g_pacc[0][(size_t)idx * 4];
    float4 b = *(const float4*)&g_pacc[1][(size_t)idx * 4];
    float r = 1.f / (g_pden[0][i * NH + h] + g_pden[1][i * NH + h]);
    float4 v = make_float4((a.x + b.x) * r, (a.y + b.y) * r,
                           (a.z + b.z) * r, (a.w + b.w) * r);
    *(float4*)&out[(size_t)idx * 4] = v;
}

// ---------------- launch ----------------
extern "C" void kernel_launch(void* const* d_in, const int* in_sizes, int n_in,
                              void* d_out, int out_size)
{
    const float* node_feats = (const float*)d_in[0];
    const int*   adj        = (const int*)d_in[1];
    const float* W          = (const float*)d_in[2];
    const float* b          = (const float*)d_in[3];
    const float* a          = (const float*)d_in[4];
    float* out = (float*)d_out;

    init_kernel<<<1, 32>>>();
    gemm_feats<<<dim3(C / 64, N_NODES / 64), 256>>>(node_feats, W, b);
    srcdst_kernel<<<N_NODES / 8, 256>>>(a);
    attn_kernel<<<dim3(NH, N_NODES / 128, NSPLIT), 256>>>(adj);
    combine_kernel<<<(N_NODES * C / 4) / 256, 256>>>(out);
}